// round 9
// baseline (speedup 1.0000x reference)
#include <cuda_runtime.h>

// ---------------------------------------------------------------------------
// CombinedRotaryEmbedding:
//   1) 64 sequential Givens column rotations  (linear, data-independent)
//   2) @ rotation_matrix (128x128)            (linear)
//   3) RoPE with per-position sin/cos
// Steps 1+2 fold into one 128x128 matrix M computed on-device per launch.
// Main kernel: y = x_row @ M  (262144 rows), then RoPE, write out.
// ---------------------------------------------------------------------------

#define N_HEAD    32
#define H_DIM     128
#define NUM_ROT   64
#define BATCH     4
#define SEQ       2048
#define TOTAL_ROWS (BATCH * SEQ * N_HEAD)      // 262144
#define CHUNK_ROWS 64
#define NUM_CHUNKS (TOTAL_ROWS / CHUNK_ROWS)   // 4096
#define TRIG_N     (SEQ * (H_DIM / 2))         // 131072

// Scratch (no cudaMalloc allowed)
__device__ float g_E[H_DIM * H_DIM];     // product of Givens rotations
__device__ float g_Mp[H_DIM * H_DIM];    // M in k-pair-interleaved layout:
                                         // g_Mp[(kp*128+c)*2 + p] = M[2*kp+p][c]
__device__ float g_sin[TRIG_N];
__device__ float g_cos[TRIG_N];

// ---------------------------------------------------------------------------
// Kernel 1: E = A1*A2*...*A64 (apply the reference's column ops to identity).
// Each of 128 threads owns one row of E (column ops are row-independent).
// ---------------------------------------------------------------------------
__global__ void k_compute_E(const float* __restrict__ thetas,
                            const float* __restrict__ rot_pairs,
                            const float* __restrict__ theta_scale) {
    __shared__ float s_c[NUM_ROT], s_s[NUM_ROT];
    __shared__ int   s_i[NUM_ROT], s_j[NUM_ROT];
    int t = threadIdx.x;
    if (t < NUM_ROT) {
        float th = thetas[t] * theta_scale[0];   // fp32 product, like the reference
        double sd, cd;
        sincos((double)th, &sd, &cd);            // fp64 trig: immune to fast-math
        s_c[t] = (float)cd;
        s_s[t] = (float)sd;
        s_i[t] = (int)rot_pairs[2 * t];
        s_j[t] = (int)rot_pairs[2 * t + 1];
    }
    __syncthreads();

    float e[H_DIM];
#pragma unroll
    for (int c = 0; c < H_DIM; c++) e[c] = (c == t) ? 1.0f : 0.0f;

    for (int k = 0; k < NUM_ROT; k++) {
        int i = s_i[k], j = s_j[k];
        float c = s_c[k], s = s_s[k];
        float xi = e[i], xj = e[j];
        if (i == j) {
            e[i] = xi * c;                       // matches ref: both sets collapse
        } else {
            e[i] = xi * c + xj * s;
            e[j] = -xi * s + xj * c;
        }
    }
    for (int c = 0; c < H_DIM; c++) g_E[t * H_DIM + c] = e[c];
}

// ---------------------------------------------------------------------------
// Kernel 2: M = E @ R, stored k-pair interleaved. One block per output row.
// ---------------------------------------------------------------------------
__global__ void k_compute_M(const float* __restrict__ R) {
    __shared__ float Er[H_DIM];
    int r = blockIdx.x;
    int c = threadIdx.x;
    Er[c] = g_E[r * H_DIM + c];
    __syncthreads();
    float acc = 0.0f;
#pragma unroll 8
    for (int k = 0; k < H_DIM; k++)
        acc = fmaf(Er[k], R[k * H_DIM + c], acc);
    g_Mp[(((unsigned)r >> 1) * H_DIM + c) * 2 + (r & 1)] = acc;
}

// ---------------------------------------------------------------------------
// Kernel 3: sin/cos tables. arg computed in fp32 (matches reference), trig in
// fp64 so accuracy holds even when the harness compiles with fast math.
// ---------------------------------------------------------------------------
__global__ void k_trig(const float* __restrict__ inv_freq) {
    int idx = blockIdx.x * blockDim.x + threadIdx.x;
    if (idx >= TRIG_N) return;
    int s = idx >> 6;
    int d = idx & 63;
    float arg = (float)s * inv_freq[d];
    double sd, cd;
    sincos((double)arg, &sd, &cd);
    g_sin[idx] = (float)sd;
    g_cos[idx] = (float)cd;
}

// ---------------------------------------------------------------------------
// Main kernel.
//  - M in SMEM, k-pair interleaved: ull Msh[kp*128 + c] = {M[2kp][c], M[2kp+1][c]}
//  - x chunk (64 rows x 128) staged in SMEM.
//  - Warp tile: 8 rows; lane owns columns {2L, 2L+1, 64+2L, 65+2L}.
//  - fma.rn.f32x2: halves accumulate even-k / odd-k partials; no pack MOVs,
//    x pairs are one 8B LDS broadcast, M pairs are one conflict-free LDS.128.
//  - Lane's columns are exactly RoPE pairs d=L and d=L+32, so the epilogue
//    is lane-local and stores coalesce (out[L], out[L+32], out[L+64], out[L+96]).
// ---------------------------------------------------------------------------
#define FMA2(acc, a, b) \
    asm("fma.rn.f32x2 %0, %1, %2, %0;" : "+l"(acc) : "l"(a), "l"(b))

__device__ __forceinline__ float2 f2unpack(unsigned long long v) {
    float2 r;
    asm("mov.b64 {%0, %1}, %2;" : "=f"(r.x), "=f"(r.y) : "l"(v));
    return r;
}

#define SMEM_M_BYTES (H_DIM * H_DIM * 4)                 // 64 KB
#define SMEM_X_BYTES (CHUNK_ROWS * H_DIM * 4)            // 32 KB
#define SMEM_BYTES   (SMEM_M_BYTES + SMEM_X_BYTES)       // 96 KB

__global__ void __launch_bounds__(256, 2)
k_main(const float* __restrict__ x, float* __restrict__ out) {
    extern __shared__ char smem[];
    unsigned long long* Msh = (unsigned long long*)smem;          // [64][128] pairs
    float* Xsh = (float*)(smem + SMEM_M_BYTES);                   // [64][128]

    // Stage M once per block (g_Mp already interleaved -> straight copy)
    {
        const float4* src = (const float4*)g_Mp;
        float4* dst = (float4*)smem;
        for (int i = threadIdx.x; i < (H_DIM * H_DIM) / 4; i += blockDim.x)
            dst[i] = src[i];
    }

    const int warp = threadIdx.x >> 5;
    const int lane = threadIdx.x & 31;
    const int r0 = warp * 8;

    for (int chunk = blockIdx.x; chunk < NUM_CHUNKS; chunk += gridDim.x) {
        const int row0 = chunk * CHUNK_ROWS;

        __syncthreads();   // Xsh reuse barrier (also covers first-iter M load)
        {
            const float4* xg = (const float4*)(x + (size_t)row0 * H_DIM);
            float4* xs = (float4*)Xsh;
#pragma unroll
            for (int i = 0; i < 8; i++)
                xs[threadIdx.x + i * 256] = xg[threadIdx.x + i * 256];
        }
        __syncthreads();

        // All 8 rows of this warp share one sequence position
        const int srow = ((row0 + r0) >> 5) & (SEQ - 1);
        const float* sb = g_sin + srow * 64;
        const float* cb = g_cos + srow * 64;
        const float sinA = sb[lane],      cosA = cb[lane];
        const float sinB = sb[lane + 32], cosB = cb[lane + 32];

        unsigned long long aA0[8], aA1[8], aB0[8], aB1[8];
#pragma unroll
        for (int r = 0; r < 8; r++) { aA0[r] = 0ull; aA1[r] = 0ull; aB0[r] = 0ull; aB1[r] = 0ull; }

        const longlong2* Mv = (const longlong2*)Msh;
#pragma unroll 2
        for (int kp = 0; kp < 64; kp++) {
            // lane's 4 columns: 2*lane, 2*lane+1 (A) and +64 (B); 16B/lane -> conflict-free LDS.128
            longlong2 mA = Mv[kp * 64 + lane];
            longlong2 mB = Mv[kp * 64 + lane + 32];
            unsigned long long mA0 = (unsigned long long)mA.x;
            unsigned long long mA1 = (unsigned long long)mA.y;
            unsigned long long mB0 = (unsigned long long)mB.x;
            unsigned long long mB1 = (unsigned long long)mB.y;
#pragma unroll
            for (int r = 0; r < 8; r++) {
                // {x[row][2kp], x[row][2kp+1]} as one 8B broadcast load
                unsigned long long xv =
                    *(const unsigned long long*)&Xsh[(r0 + r) * H_DIM + 2 * kp];
                FMA2(aA0[r], xv, mA0);
                FMA2(aA1[r], xv, mA1);
                FMA2(aB0[r], xv, mB0);
                FMA2(aB1[r], xv, mB1);
            }
        }

        // Epilogue: reduce halves, apply RoPE, coalesced scalar stores
#pragma unroll
        for (int r = 0; r < 8; r++) {
            float2 vA0 = f2unpack(aA0[r]);
            float2 vA1 = f2unpack(aA1[r]);
            float2 vB0 = f2unpack(aB0[r]);
            float2 vB1 = f2unpack(aB1[r]);
            float yA0 = vA0.x + vA0.y;   // y[2L]      -> pair d = L
            float yA1 = vA1.x + vA1.y;   // y[2L+1]
            float yB0 = vB0.x + vB0.y;   // y[64+2L]   -> pair d = L+32
            float yB1 = vB1.x + vB1.y;   // y[65+2L]

            float* o = out + (size_t)(row0 + r0 + r) * H_DIM;
            o[lane]      = yA0 * cosA - yA1 * sinA;   // out[d],    d = L
            o[lane + 64] = yA0 * sinA + yA1 * cosA;   // out[d+64]
            o[lane + 32] = yB0 * cosB - yB1 * sinB;   // out[d],    d = L+32
            o[lane + 96] = yB0 * sinB + yB1 * cosB;   // out[d+64]
        }
    }
}

// ---------------------------------------------------------------------------
// Launch. Inputs (metadata order): x, thetas, rotation_pairs, theta_scale,
// rotation_matrix, inv_freq, n_head (unused; n_head=32 is baked in).
// ---------------------------------------------------------------------------
extern "C" void kernel_launch(void* const* d_in, const int* in_sizes, int n_in,
                              void* d_out, int out_size) {
    const float* x      = (const float*)d_in[0];
    const float* thetas = (const float*)d_in[1];
    const float* rpairs = (const float*)d_in[2];
    const float* tscale = (const float*)d_in[3];
    const float* rotmat = (const float*)d_in[4];
    const float* invfrq = (const float*)d_in[5];
    float* out = (float*)d_out;

    (void)in_sizes; (void)n_in; (void)out_size;

    cudaFuncSetAttribute(k_main, cudaFuncAttributeMaxDynamicSharedMemorySize,
                         SMEM_BYTES);

    k_compute_E<<<1, H_DIM>>>(thetas, rpairs, tscale);
    k_compute_M<<<H_DIM, H_DIM>>>(rotmat);
    k_trig<<<(TRIG_N + 255) / 256, 256>>>(invfrq);
    k_main<<<304, 256, SMEM_BYTES>>>(x, out);
}

// round 10
// speedup vs baseline: 1.0518x; 1.0518x over previous
#include <cuda_runtime.h>

// ---------------------------------------------------------------------------
// CombinedRotaryEmbedding:
//   1) 64 sequential Givens column rotations  (linear, data-independent)
//   2) @ rotation_matrix (128x128)            (linear)
//   3) RoPE with per-position sin/cos
// Steps 1+2 fold into one 128x128 matrix M computed on-device per launch.
// Main kernel: y = x_row @ M  (262144 rows), then RoPE, write out.
// ---------------------------------------------------------------------------

#define N_HEAD    32
#define H_DIM     128
#define NUM_ROT   64
#define BATCH     4
#define SEQ       2048
#define TOTAL_ROWS (BATCH * SEQ * N_HEAD)      // 262144
#define CHUNK_ROWS 64
#define NUM_CHUNKS (TOTAL_ROWS / CHUNK_ROWS)   // 4096
#define TRIG_N     (SEQ * (H_DIM / 2))         // 131072

// Scratch (no cudaMalloc allowed)
__device__ float g_E[H_DIM * H_DIM];     // product of Givens rotations
__device__ float g_Mp[H_DIM * H_DIM];    // M in k-pair-interleaved layout:
                                         // g_Mp[(kp*128+c)*2 + p] = M[2*kp+p][c]
__device__ float g_sin[TRIG_N];
__device__ float g_cos[TRIG_N];

// ---------------------------------------------------------------------------
// Kernel 1: E = A1*A2*...*A64 (apply the reference's column ops to identity).
// Each of 128 threads owns one row of E (column ops are row-independent).
// ---------------------------------------------------------------------------
__global__ void k_compute_E(const float* __restrict__ thetas,
                            const float* __restrict__ rot_pairs,
                            const float* __restrict__ theta_scale) {
    __shared__ float s_c[NUM_ROT], s_s[NUM_ROT];
    __shared__ int   s_i[NUM_ROT], s_j[NUM_ROT];
    int t = threadIdx.x;
    if (t < NUM_ROT) {
        float th = thetas[t] * theta_scale[0];   // fp32 product, like the reference
        double sd, cd;
        sincos((double)th, &sd, &cd);            // fp64 trig: immune to fast-math
        s_c[t] = (float)cd;
        s_s[t] = (float)sd;
        s_i[t] = (int)rot_pairs[2 * t];
        s_j[t] = (int)rot_pairs[2 * t + 1];
    }
    __syncthreads();

    float e[H_DIM];
#pragma unroll
    for (int c = 0; c < H_DIM; c++) e[c] = (c == t) ? 1.0f : 0.0f;

    for (int k = 0; k < NUM_ROT; k++) {
        int i = s_i[k], j = s_j[k];
        float c = s_c[k], s = s_s[k];
        float xi = e[i], xj = e[j];
        if (i == j) {
            e[i] = xi * c;                       // matches ref: both sets collapse
        } else {
            e[i] = xi * c + xj * s;
            e[j] = -xi * s + xj * c;
        }
    }
    for (int c = 0; c < H_DIM; c++) g_E[t * H_DIM + c] = e[c];
}

// ---------------------------------------------------------------------------
// Kernel 2: M = E @ R, stored k-pair interleaved. One block per output row.
// ---------------------------------------------------------------------------
__global__ void k_compute_M(const float* __restrict__ R) {
    __shared__ float Er[H_DIM];
    int r = blockIdx.x;
    int c = threadIdx.x;
    Er[c] = g_E[r * H_DIM + c];
    __syncthreads();
    float acc = 0.0f;
#pragma unroll 8
    for (int k = 0; k < H_DIM; k++)
        acc = fmaf(Er[k], R[k * H_DIM + c], acc);
    g_Mp[(((unsigned)r >> 1) * H_DIM + c) * 2 + (r & 1)] = acc;
}

// ---------------------------------------------------------------------------
// Kernel 3: sin/cos tables. arg computed in fp32 (matches reference), trig in
// fp64 so accuracy holds even when the harness compiles with fast math.
// ---------------------------------------------------------------------------
__global__ void k_trig(const float* __restrict__ inv_freq) {
    int idx = blockIdx.x * blockDim.x + threadIdx.x;
    if (idx >= TRIG_N) return;
    int s = idx >> 6;
    int d = idx & 63;
    float arg = (float)s * inv_freq[d];
    double sd, cd;
    sincos((double)arg, &sd, &cd);
    g_sin[idx] = (float)sd;
    g_cos[idx] = (float)cd;
}

// ---------------------------------------------------------------------------
// Main kernel.
//  - M in SMEM, k-pair interleaved: ull Msh[kp*128 + c] = {M[2kp][c], M[2kp+1][c]}
//  - x chunk (64 rows x 128) staged in SMEM.
//  - Warp tile: 8 rows; lane owns columns {2L, 2L+1, 64+2L, 65+2L}.
//  - fma.rn.f32x2: halves accumulate even-k / odd-k partials; no pack MOVs,
//    x pairs are one 8B LDS broadcast, M pairs are one conflict-free LDS.128.
//  - Lane's columns are exactly RoPE pairs d=L and d=L+32, so the epilogue
//    is lane-local and stores coalesce (out[L], out[L+32], out[L+64], out[L+96]).
// ---------------------------------------------------------------------------
#define FMA2(acc, a, b) \
    asm("fma.rn.f32x2 %0, %1, %2, %0;" : "+l"(acc) : "l"(a), "l"(b))

__device__ __forceinline__ float2 f2unpack(unsigned long long v) {
    float2 r;
    asm("mov.b64 {%0, %1}, %2;" : "=f"(r.x), "=f"(r.y) : "l"(v));
    return r;
}

#define SMEM_M_BYTES (H_DIM * H_DIM * 4)                 // 64 KB
#define SMEM_X_BYTES (CHUNK_ROWS * H_DIM * 4)            // 32 KB
#define SMEM_BYTES   (SMEM_M_BYTES + SMEM_X_BYTES)       // 96 KB

__global__ void __launch_bounds__(256, 2)
k_main(const float* __restrict__ x, float* __restrict__ out) {
    extern __shared__ char smem[];
    unsigned long long* Msh = (unsigned long long*)smem;          // [64][128] pairs
    float* Xsh = (float*)(smem + SMEM_M_BYTES);                   // [64][128]

    // Stage M once per block (g_Mp already interleaved -> straight copy)
    {
        const float4* src = (const float4*)g_Mp;
        float4* dst = (float4*)smem;
        for (int i = threadIdx.x; i < (H_DIM * H_DIM) / 4; i += blockDim.x)
            dst[i] = src[i];
    }

    const int warp = threadIdx.x >> 5;
    const int lane = threadIdx.x & 31;
    const int r0 = warp * 8;

    for (int chunk = blockIdx.x; chunk < NUM_CHUNKS; chunk += gridDim.x) {
        const int row0 = chunk * CHUNK_ROWS;

        __syncthreads();   // Xsh reuse barrier (also covers first-iter M load)
        {
            const float4* xg = (const float4*)(x + (size_t)row0 * H_DIM);
            float4* xs = (float4*)Xsh;
#pragma unroll
            for (int i = 0; i < 8; i++)
                xs[threadIdx.x + i * 256] = xg[threadIdx.x + i * 256];
        }
        __syncthreads();

        // All 8 rows of this warp share one sequence position
        const int srow = ((row0 + r0) >> 5) & (SEQ - 1);
        const float* sb = g_sin + srow * 64;
        const float* cb = g_cos + srow * 64;
        const float sinA = sb[lane],      cosA = cb[lane];
        const float sinB = sb[lane + 32], cosB = cb[lane + 32];

        unsigned long long aA0[8], aA1[8], aB0[8], aB1[8];
#pragma unroll
        for (int r = 0; r < 8; r++) { aA0[r] = 0ull; aA1[r] = 0ull; aB0[r] = 0ull; aB1[r] = 0ull; }

        const longlong2* Mv = (const longlong2*)Msh;
#pragma unroll 2
        for (int kp = 0; kp < 64; kp++) {
            // lane's 4 columns: 2*lane, 2*lane+1 (A) and +64 (B); 16B/lane -> conflict-free LDS.128
            longlong2 mA = Mv[kp * 64 + lane];
            longlong2 mB = Mv[kp * 64 + lane + 32];
            unsigned long long mA0 = (unsigned long long)mA.x;
            unsigned long long mA1 = (unsigned long long)mA.y;
            unsigned long long mB0 = (unsigned long long)mB.x;
            unsigned long long mB1 = (unsigned long long)mB.y;
#pragma unroll
            for (int r = 0; r < 8; r++) {
                // {x[row][2kp], x[row][2kp+1]} as one 8B broadcast load
                unsigned long long xv =
                    *(const unsigned long long*)&Xsh[(r0 + r) * H_DIM + 2 * kp];
                FMA2(aA0[r], xv, mA0);
                FMA2(aA1[r], xv, mA1);
                FMA2(aB0[r], xv, mB0);
                FMA2(aB1[r], xv, mB1);
            }
        }

        // Epilogue: reduce halves, apply RoPE, coalesced scalar stores
#pragma unroll
        for (int r = 0; r < 8; r++) {
            float2 vA0 = f2unpack(aA0[r]);
            float2 vA1 = f2unpack(aA1[r]);
            float2 vB0 = f2unpack(aB0[r]);
            float2 vB1 = f2unpack(aB1[r]);
            float yA0 = vA0.x + vA0.y;   // y[2L]      -> pair d = L
            float yA1 = vA1.x + vA1.y;   // y[2L+1]
            float yB0 = vB0.x + vB0.y;   // y[64+2L]   -> pair d = L+32
            float yB1 = vB1.x + vB1.y;   // y[65+2L]

            float* o = out + (size_t)(row0 + r0 + r) * H_DIM;
            o[lane]      = yA0 * cosA - yA1 * sinA;   // out[d],    d = L
            o[lane + 64] = yA0 * sinA + yA1 * cosA;   // out[d+64]
            o[lane + 32] = yB0 * cosB - yB1 * sinB;   // out[d],    d = L+32
            o[lane + 96] = yB0 * sinB + yB1 * cosB;   // out[d+64]
        }
    }
}

// ---------------------------------------------------------------------------
// Launch. Inputs (metadata order): x, thetas, rotation_pairs, theta_scale,
// rotation_matrix, inv_freq, n_head (unused; n_head=32 is baked in).
// ---------------------------------------------------------------------------
extern "C" void kernel_launch(void* const* d_in, const int* in_sizes, int n_in,
                              void* d_out, int out_size) {
    const float* x      = (const float*)d_in[0];
    const float* thetas = (const float*)d_in[1];
    const float* rpairs = (const float*)d_in[2];
    const float* tscale = (const float*)d_in[3];
    const float* rotmat = (const float*)d_in[4];
    const float* invfrq = (const float*)d_in[5];
    float* out = (float*)d_out;

    (void)in_sizes; (void)n_in; (void)out_size;

    cudaFuncSetAttribute(k_main, cudaFuncAttributeMaxDynamicSharedMemorySize,
                         SMEM_BYTES);

    k_compute_E<<<1, H_DIM>>>(thetas, rpairs, tscale);
    k_compute_M<<<H_DIM, H_DIM>>>(rotmat);
    k_trig<<<(TRIG_N + 255) / 256, 256>>>(invfrq);
    k_main<<<304, 256, SMEM_BYTES>>>(x, out);
}